// round 2
// baseline (speedup 1.0000x reference)
#include <cuda_runtime.h>
#include <cstdint>
#include <math.h>

#define BB 4
#define NN 1024
#define PP 42
#define DD 96
#define PD 4032          // PP*DD
#define KNODE 8
#define KCAND 12         // fp32 prepass candidates (margin over 8)
#define KTOK 8
#define POUT 50          // PP + KTOK
#define EPSD 1e-7

#define NEG_INF __int_as_float(0xff800000)
#define NEG_INF_D (-1.0e300)

// ---------------- scratch (device globals; no allocation) ----------------
__device__ float  g_sim[BB * NN * NN];        // raw fp32 dot products, 16.78 MB
__device__ double g_inv_node_d[BB * NN];      // exact 1/(||flat_row|| + eps)
__device__ float  g_inv_node_f[BB * NN];
__device__ double g_inv_tok_d[BB * NN * PP];  // exact 1/(||token|| + eps)
__device__ int    g_cand[BB * NN * KCAND];    // fp32 top-12 node candidates

// ---------------- compensated arithmetic helpers --------------------------
__device__ __forceinline__ void two_sum(float a, float b, float& s, float& e) {
    s = a + b;
    float z = s - a;
    e = (a - (s - z)) + (b - z);
}
__device__ __forceinline__ void dot2_step(float a, float b, float& hi, float& lo) {
    float p = a * b;
    float ep = fmaf(a, b, -p);
    float s, e;
    two_sum(hi, p, s, e);
    hi = s;
    lo += e + ep;
}

// =========================================================================
// K1: exact token norms + node norms (compensated fp32 -> fp64).
// One block per (b,n), 128 threads (4 warps).
// =========================================================================
__global__ __launch_bounds__(128) void k_norms(const float* __restrict__ h) {
    int bn = blockIdx.x;
    const float* base = h + (size_t)bn * PD;
    __shared__ double s_node[4];
    int warp = threadIdx.x >> 5, lane = threadIdx.x & 31;
    double nodesum = 0.0;
    for (int p = warp; p < PP; p += 4) {
        const float* tp = base + p * DD;
        float hi = 0.f, lo = 0.f;
        float v0 = tp[lane], v1 = tp[lane + 32], v2 = tp[lane + 64];
        dot2_step(v0, v0, hi, lo);
        dot2_step(v1, v1, hi, lo);
        dot2_step(v2, v2, hi, lo);
        double s = (double)hi + (double)lo;
        #pragma unroll
        for (int o = 16; o; o >>= 1) s += __shfl_xor_sync(0xffffffffu, s, o);
        if (lane == 0) g_inv_tok_d[bn * PP + p] = 1.0 / (sqrt(s) + EPSD);
        nodesum += s;
    }
    if (lane == 0) s_node[warp] = nodesum;
    __syncthreads();
    if (threadIdx.x == 0) {
        double t = s_node[0] + s_node[1] + s_node[2] + s_node[3];
        double inv = 1.0 / (sqrt(t) + EPSD);
        g_inv_node_d[bn] = inv;
        g_inv_node_f[bn] = (float)inv;
    }
}

// =========================================================================
// K2: sim = flat @ flat^T per batch (raw fp32 dots).  128x128 tile, BK=16,
// 256 threads, 8x8 per thread.
// =========================================================================
#define BM 128
#define BN_ 128
#define BK 16

__global__ __launch_bounds__(256) void k_sim(const float* __restrict__ h) {
    int b = blockIdx.z;
    int rowBase = blockIdx.y * BM;
    int colBase = blockIdx.x * BN_;
    const float* A = h + (size_t)b * NN * PD;

    __shared__ float As[BK][BM + 4];
    __shared__ float Bs[BK][BN_ + 4];

    int t = threadIdx.x;
    int tx = t & 15, ty = t >> 4;

    float acc[8][8];
    #pragma unroll
    for (int i = 0; i < 8; i++)
        #pragma unroll
        for (int j = 0; j < 8; j++) acc[i][j] = 0.f;

    for (int k0 = 0; k0 < PD; k0 += BK) {
        #pragma unroll
        for (int u0 = 0; u0 < 2; u0++) {
            int u = t + u0 * 256;
            int r = u >> 2, c4 = u & 3;
            float4 v = *(const float4*)(A + (size_t)(rowBase + r) * PD + k0 + c4 * 4);
            As[c4 * 4 + 0][r] = v.x; As[c4 * 4 + 1][r] = v.y;
            As[c4 * 4 + 2][r] = v.z; As[c4 * 4 + 3][r] = v.w;
            float4 w = *(const float4*)(A + (size_t)(colBase + r) * PD + k0 + c4 * 4);
            Bs[c4 * 4 + 0][r] = w.x; Bs[c4 * 4 + 1][r] = w.y;
            Bs[c4 * 4 + 2][r] = w.z; Bs[c4 * 4 + 3][r] = w.w;
        }
        __syncthreads();
        #pragma unroll
        for (int kk = 0; kk < BK; kk++) {
            float a[8], bb[8];
            #pragma unroll
            for (int i = 0; i < 8; i++) a[i] = As[kk][ty * 8 + i];
            #pragma unroll
            for (int j = 0; j < 8; j++) bb[j] = Bs[kk][tx * 8 + j];
            #pragma unroll
            for (int i = 0; i < 8; i++)
                #pragma unroll
                for (int j = 0; j < 8; j++) acc[i][j] += a[i] * bb[j];
        }
        __syncthreads();
    }

    float* C = g_sim + (size_t)b * NN * NN;
    #pragma unroll
    for (int i = 0; i < 8; i++) {
        int r = rowBase + ty * 8 + i;
        #pragma unroll
        for (int j = 0; j < 8; j += 4) {
            float4 v = make_float4(acc[i][j], acc[i][j + 1], acc[i][j + 2], acc[i][j + 3]);
            *(float4*)(C + (size_t)r * NN + colBase + tx * 8 + j) = v;
        }
    }
}

// =========================================================================
// K3: fp32 prepass — normalize row, zero diag, select top-12 candidates.
// One block per (b,n), 256 threads.
// =========================================================================
__global__ __launch_bounds__(256) void k_topk_node() {
    int bn = blockIdx.x;
    int b = bn >> 10, n = bn & 1023;
    __shared__ float vals[NN];
    __shared__ float rv[256];
    __shared__ int   ri[256];
    int t = threadIdx.x;
    float invn = g_inv_node_f[bn];
    const float* row = g_sim + (size_t)b * NN * NN + (size_t)n * NN;
    for (int m = t; m < NN; m += 256) {
        vals[m] = (m == n) ? 0.f : row[m] * invn * g_inv_node_f[b * NN + m];
    }
    __syncthreads();
    for (int k = 0; k < KCAND; k++) {
        float bv = NEG_INF; int bi = 0;
        for (int m = t; m < NN; m += 256) {
            float v = vals[m];
            if (v > bv) { bv = v; bi = m; }
        }
        rv[t] = bv; ri[t] = bi;
        __syncthreads();
        for (int s = 128; s > 0; s >>= 1) {
            if (t < s) {
                float v2 = rv[t + s]; int i2 = ri[t + s];
                if (v2 > rv[t] || (v2 == rv[t] && i2 < ri[t])) { rv[t] = v2; ri[t] = i2; }
            }
            __syncthreads();
        }
        if (t == 0) {
            g_cand[bn * KCAND + k] = ri[0];
            vals[ri[0]] = NEG_INF;
        }
        __syncthreads();
    }
}

// =========================================================================
// K4: exact node re-rank (compensated dots over 12 candidates) -> top-8,
//     exact token-level cosine over 8*42=336 candidates -> top-8,
//     fused linear (x @ W^T + b + neighbor_token) -> out[:, :, 42:50, :].
// One block per (b,n), 256 threads.  Dynamic smem ~74 KB.
// =========================================================================
__global__ __launch_bounds__(256) void k_tok(const float* __restrict__ h,
                                             const float* __restrict__ W,
                                             const float* __restrict__ bias,
                                             const float* __restrict__ ntok,
                                             float* __restrict__ out) {
    extern __shared__ char dynv[];
    double* ssim = (double*)dynv;                 // 336
    double* rvd  = ssim + 336;                    // 256
    double* ex12 = rvd + 256;                     // 12
    float*  s_big = (float*)(ex12 + 12);          // 16128 (flat_n, reused as W[e*97+d])
    float*  stok  = s_big + 16128;                // 8*96
    float*  sq    = stok + KTOK * DD;             // 96
    int*    ri    = (int*)(sq + DD);              // 256
    int*    scand = ri + 256;                     // 12
    int*    snode = scand + KCAND;                // 8
    int*    cm    = snode + KNODE;                // 8
    int*    cp    = cm + KTOK;                    // 8

    int bn = blockIdx.x;
    int b = bn >> 10;
    int t = threadIdx.x, warp = t >> 5, lane = t & 31;

    // stage query token, candidates, and flat_n
    if (t < DD) sq[t] = h[((size_t)bn * PP + (PP - 1)) * (size_t)DD + t];
    if (t < KCAND) scand[t] = g_cand[bn * KCAND + t];
    const float* fn = h + (size_t)bn * PD;
    for (int i = t; i < PD; i += 256) s_big[i] = fn[i];
    __syncthreads();

    // ---- exact node sims for 12 candidates ----
    for (int c = warp; c < KCAND; c += 8) {
        int m = scand[c];
        const float* fm = h + (size_t)(b * NN + m) * PD;
        float hi = 0.f, lo = 0.f;
        for (int i = lane; i < PD; i += 32) dot2_step(s_big[i], fm[i], hi, lo);
        double v = (double)hi + (double)lo;
        #pragma unroll
        for (int o = 16; o; o >>= 1) v += __shfl_xor_sync(0xffffffffu, v, o);
        if (lane == 0) ex12[c] = v * g_inv_node_d[bn] * g_inv_node_d[b * NN + m];
    }
    __syncthreads();

    if (t == 0) {
        // exact top-8 of 12 (value desc, tie -> lower node index)
        unsigned used = 0;
        for (int k = 0; k < KNODE; k++) {
            int best = -1;
            for (int j = 0; j < KCAND; j++) {
                if (used & (1u << j)) continue;
                if (best < 0 || ex12[j] > ex12[best] ||
                    (ex12[j] == ex12[best] && scand[j] < scand[best])) best = j;
            }
            used |= (1u << best);
            snode[k] = scand[best];
        }
    }
    __syncthreads();

    // reuse s_big for W (transposed-padded): sW[e*97+d]
    for (int i = t; i < DD * DD; i += 256) {
        int e = i / DD, d = i - e * DD;
        s_big[e * 97 + d] = W[i];
    }

    // ---- exact token sims for 336 candidates ----
    double qinv = g_inv_tok_d[bn * PP + PP - 1];
    for (int c = warp; c < KNODE * PP; c += 8) {
        int kn = c / PP, p = c - kn * PP;
        int m = snode[kn];
        const float* tp = h + (((size_t)(b * NN + m)) * PP + p) * (size_t)DD;
        float hi = 0.f, lo = 0.f;
        dot2_step(tp[lane],      sq[lane],      hi, lo);
        dot2_step(tp[lane + 32], sq[lane + 32], hi, lo);
        dot2_step(tp[lane + 64], sq[lane + 64], hi, lo);
        double v = (double)hi + (double)lo;
        #pragma unroll
        for (int o = 16; o; o >>= 1) v += __shfl_xor_sync(0xffffffffu, v, o);
        if (lane == 0) ssim[c] = v * qinv * g_inv_tok_d[(b * NN + m) * PP + p];
    }
    __syncthreads();

    // ---- exact top-8 of 336 (value desc, tie -> lower candidate index) ----
    for (int k = 0; k < KTOK; k++) {
        double bv = NEG_INF_D; int bi = 0;
        for (int c = t; c < KNODE * PP; c += 256) {
            double v = ssim[c];
            if (v > bv) { bv = v; bi = c; }
        }
        rvd[t] = bv; ri[t] = bi;
        __syncthreads();
        for (int s = 128; s > 0; s >>= 1) {
            if (t < s) {
                double v2 = rvd[t + s]; int i2 = ri[t + s];
                if (v2 > rvd[t] || (v2 == rvd[t] && i2 < ri[t])) { rvd[t] = v2; ri[t] = i2; }
            }
            __syncthreads();
        }
        if (t == 0) {
            int c = ri[0]; int kn = c / PP, p = c - kn * PP;
            cm[k] = snode[kn]; cp[k] = p;
            ssim[c] = NEG_INF_D;
        }
        __syncthreads();
    }

    // gather selected tokens
    for (int i = t; i < KTOK * DD; i += 256) {
        int k = i / DD, d = i - k * DD;
        stok[k * DD + d] = h[(((size_t)(b * NN + cm[k])) * PP + cp[k]) * (size_t)DD + d];
    }
    __syncthreads();

    float nt = ntok[0];
    // sk = stok @ W^T + bias + nt
    for (int o = t; o < KTOK * DD; o += 256) {
        int k = o / DD, e = o - k * DD;
        float acc = bias[e] + nt;
        #pragma unroll 8
        for (int d = 0; d < DD; d++) acc += stok[k * DD + d] * s_big[e * 97 + d];
        out[(((size_t)bn) * POUT + PP + k) * (size_t)DD + e] = acc;
    }
}

// =========================================================================
// K5: hf = h @ W^T + b -> out[:, :, 0:42, :].  64 rows x 96 cols per block.
// =========================================================================
__global__ __launch_bounds__(256) void k_hf(const float* __restrict__ h,
                                            const float* __restrict__ W,
                                            const float* __restrict__ bias,
                                            float* __restrict__ out) {
    extern __shared__ float dyn[];
    float* sXT = dyn;                 // [DD][65]
    float* sWT = dyn + DD * 65;       // [DD][97]

    int r0 = blockIdx.x * 64;
    int t = threadIdx.x;

    const float* Xbase = h + (size_t)r0 * DD;
    for (int i = t; i < 64 * DD; i += 256) {
        int r = i / DD, d = i - r * DD;
        sXT[d * 65 + r] = Xbase[i];
    }
    for (int i = t; i < DD * DD; i += 256) {
        int e = i / DD, d = i - e * DD;
        sWT[d * 97 + e] = W[i];
    }
    __syncthreads();

    int tx = t & 15, ty = t >> 4;
    float acc[4][6];
    #pragma unroll
    for (int i = 0; i < 4; i++)
        #pragma unroll
        for (int j = 0; j < 6; j++) acc[i][j] = bias[tx * 6 + j];

    #pragma unroll 4
    for (int d = 0; d < DD; d++) {
        float x[4], w[6];
        #pragma unroll
        for (int i = 0; i < 4; i++) x[i] = sXT[d * 65 + ty * 4 + i];
        #pragma unroll
        for (int j = 0; j < 6; j++) w[j] = sWT[d * 97 + tx * 6 + j];
        #pragma unroll
        for (int i = 0; i < 4; i++)
            #pragma unroll
            for (int j = 0; j < 6; j++) acc[i][j] += x[i] * w[j];
    }

    #pragma unroll
    for (int i = 0; i < 4; i++) {
        int r = r0 + ty * 4 + i;
        int bn = r / PP, p = r - bn * PP;
        float* orow = out + (((size_t)bn) * POUT + p) * (size_t)DD + tx * 6;
        #pragma unroll
        for (int j = 0; j < 6; j++) orow[j] = acc[i][j];
    }
}

// =========================================================================
extern "C" void kernel_launch(void* const* d_in, const int* in_sizes, int n_in,
                              void* d_out, int out_size) {
    const float* h    = (const float*)d_in[0];
    const float* W    = (const float*)d_in[1];
    const float* bias = (const float*)d_in[2];
    const float* ntok = (const float*)d_in[3];
    float* out = (float*)d_out;

    k_norms<<<BB * NN, 128>>>(h);

    dim3 g2(NN / BN_, NN / BM, BB);
    k_sim<<<g2, 256>>>(h);

    k_topk_node<<<BB * NN, 256>>>();

    size_t tok_smem = (336 + 256 + 12) * sizeof(double) +
                      (16128 + KTOK * DD + DD) * sizeof(float) +
                      (256 + KCAND + KNODE + KTOK + KTOK) * sizeof(int) + 64;
    cudaFuncSetAttribute(k_tok, cudaFuncAttributeMaxDynamicSharedMemorySize, (int)tok_smem);
    k_tok<<<BB * NN, 256, tok_smem>>>(h, W, bias, ntok, out);

    size_t hf_smem = (size_t)(DD * 65 + DD * 97) * sizeof(float);  // 62208 B
    cudaFuncSetAttribute(k_hf, cudaFuncAttributeMaxDynamicSharedMemorySize, (int)hf_smem);
    k_hf<<<(BB * NN * PP) / 64, 256, hf_smem>>>(h, W, bias, out);
}

// round 4
// speedup vs baseline: 1.3973x; 1.3973x over previous
#include <cuda_runtime.h>
#include <cuda_bf16.h>
#include <cstdint>
#include <math.h>

#define BB 4
#define NN 1024
#define PP 42
#define DD 96
#define PD 4032          // PP*DD
#define KNODE 8
#define KCAND 12         // prepass candidates (margin over 8)
#define KTOK 8
#define POUT 50          // PP + KTOK
#define EPSD 1e-7

#define NEG_INF __int_as_float(0xff800000)
#define NEG_INF_D (-1.0e300)

// ---------------- scratch (device globals; no allocation) ----------------
__device__ float  g_sim[BB * NN * NN];        // prepass dots (fp32 out of mma)
__device__ __align__(16) __nv_bfloat16 g_hbf[BB * NN * PD];  // bf16 copy of h
__device__ double g_inv_node_d[BB * NN];
__device__ float  g_inv_node_f[BB * NN];
__device__ double g_inv_tok_d[BB * NN * PP];
__device__ int    g_cand[BB * NN * KCAND];

// ---------------- compensated arithmetic helpers --------------------------
__device__ __forceinline__ void two_sum(float a, float b, float& s, float& e) {
    s = a + b;
    float z = s - a;
    e = (a - (s - z)) + (b - z);
}
__device__ __forceinline__ void dot2_step(float a, float b, float& hi, float& lo) {
    float p = a * b;
    float ep = fmaf(a, b, -p);
    float s, e;
    two_sum(hi, p, s, e);
    hi = s;
    lo += e + ep;
}

__device__ __forceinline__ void cp16(uint32_t s, const void* g) {
    asm volatile("cp.async.cg.shared.global [%0], [%1], 16;\n" :: "r"(s), "l"(g));
}

// =========================================================================
// K0: h (fp32) -> g_hbf (bf16).
// =========================================================================
__global__ __launch_bounds__(256) void k_conv(const float* __restrict__ h) {
    size_t i = ((size_t)blockIdx.x * 256 + threadIdx.x) * 4;
    float4 v = *(const float4*)(h + i);
    __nv_bfloat162 lo = __floats2bfloat162_rn(v.x, v.y);
    __nv_bfloat162 hi = __floats2bfloat162_rn(v.z, v.w);
    uint2 pk;
    pk.x = *(uint32_t*)&lo;
    pk.y = *(uint32_t*)&hi;
    *(uint2*)(&g_hbf[i]) = pk;
}

// =========================================================================
// K1: exact token norms + node norms (compensated fp32 -> fp64).
// =========================================================================
__global__ __launch_bounds__(128) void k_norms(const float* __restrict__ h) {
    int bn = blockIdx.x;
    const float* base = h + (size_t)bn * PD;
    __shared__ double s_node[4];
    int warp = threadIdx.x >> 5, lane = threadIdx.x & 31;
    double nodesum = 0.0;
    for (int p = warp; p < PP; p += 4) {
        const float* tp = base + p * DD;
        float hi = 0.f, lo = 0.f;
        float v0 = tp[lane], v1 = tp[lane + 32], v2 = tp[lane + 64];
        dot2_step(v0, v0, hi, lo);
        dot2_step(v1, v1, hi, lo);
        dot2_step(v2, v2, hi, lo);
        double s = (double)hi + (double)lo;
        #pragma unroll
        for (int o = 16; o; o >>= 1) s += __shfl_xor_sync(0xffffffffu, s, o);
        if (lane == 0) g_inv_tok_d[bn * PP + p] = 1.0 / (sqrt(s) + EPSD);
        nodesum += s;
    }
    if (lane == 0) s_node[warp] = nodesum;
    __syncthreads();
    if (threadIdx.x == 0) {
        double t = s_node[0] + s_node[1] + s_node[2] + s_node[3];
        double inv = 1.0 / (sqrt(t) + EPSD);
        g_inv_node_d[bn] = inv;
        g_inv_node_f[bn] = (float)inv;
    }
}

// =========================================================================
// K2: bf16 tensor-core prepass GEMM: g_sim = flat_bf16 @ flat_bf16^T.
// CTA tile 128x128, BK=64, cp.async double buffer, mma.sync m16n8k16.
// B tile has identical storage to A ([row][k] k-contiguous), so BOTH
// operands use non-trans ldmatrix (B fragment pairs are k-consecutive at
// fixed n — exactly what non-trans delivers from k-major rows).
// =========================================================================
__global__ void __launch_bounds__(256, 2) k_sim_mma() {
    extern __shared__ __align__(16) unsigned char smraw[];
    const int t = threadIdx.x;
    const int lane = t & 31, warp = t >> 5;
    const int warp_m = warp >> 2, warp_n = warp & 3;
    const int bz = blockIdx.z;
    const int rowBase = blockIdx.y * 128, colBase = blockIdx.x * 128;
    const __nv_bfloat16* base = g_hbf + (size_t)bz * NN * PD;
    uint32_t s0 = (uint32_t)__cvta_generic_to_shared(smraw);

    float acc[4][4][4];
    #pragma unroll
    for (int i = 0; i < 4; i++)
        #pragma unroll
        for (int j = 0; j < 4; j++)
            #pragma unroll
            for (int q = 0; q < 4; q++) acc[i][j][q] = 0.f;

    // ---- async tile loader: A rows from rowBase, B rows from colBase ----
    auto issue = [&](int it, int buf) {
        int k0 = it * 64;
        uint32_t sbuf = s0 + buf * 32768;
        #pragma unroll
        for (int i = 0; i < 4; i++) {
            int u = t + 256 * i;
            int r = u >> 3, c = u & 7;
            uint32_t soff = r * 128 + ((c ^ (r & 7)) << 4);
            cp16(sbuf + soff, base + (size_t)(rowBase + r) * PD + k0 + c * 8);
            cp16(sbuf + 16384 + soff, base + (size_t)(colBase + r) * PD + k0 + c * 8);
        }
        asm volatile("cp.async.commit_group;\n");
    };

    issue(0, 0);
    for (int it = 0; it < 63; it++) {
        if (it < 62) {
            issue(it + 1, (it + 1) & 1);
            asm volatile("cp.async.wait_group 1;\n");
        } else {
            asm volatile("cp.async.wait_group 0;\n");
        }
        __syncthreads();
        uint32_t sA = s0 + (it & 1) * 32768;
        uint32_t sB = sA + 16384;
        #pragma unroll
        for (int kk = 0; kk < 4; kk++) {
            uint32_t a[4][4], bf[4][2];
            #pragma unroll
            for (int mi = 0; mi < 4; mi++) {
                int row = warp_m * 64 + mi * 16 + ((lane >> 3) & 1) * 8 + (lane & 7);
                int ch = kk * 2 + (lane >> 4);
                uint32_t addr = sA + row * 128 + ((ch ^ (row & 7)) << 4);
                asm volatile("ldmatrix.sync.aligned.m8n8.x4.shared.b16 {%0,%1,%2,%3}, [%4];\n"
                    : "=r"(a[mi][0]), "=r"(a[mi][1]), "=r"(a[mi][2]), "=r"(a[mi][3]) : "r"(addr));
            }
            #pragma unroll
            for (int call = 0; call < 2; call++) {
                // matrices: lanes0-7 -> (n0-7,k0-7)=b0 blk0; lanes8-15 -> (n0-7,k8-15)=b1 blk0;
                //           lanes16-23 -> (n8-15,k0-7)=b0 blk1; lanes24-31 -> b1 blk1.
                int row = warp_n * 32 + call * 16 + ((lane >> 4) & 1) * 8 + (lane & 7);
                int ch = kk * 2 + ((lane >> 3) & 1);
                uint32_t addr = sB + row * 128 + ((ch ^ (row & 7)) << 4);
                uint32_t r0, r1, r2, r3;
                asm volatile("ldmatrix.sync.aligned.m8n8.x4.shared.b16 {%0,%1,%2,%3}, [%4];\n"
                    : "=r"(r0), "=r"(r1), "=r"(r2), "=r"(r3) : "r"(addr));
                bf[call * 2][0] = r0; bf[call * 2][1] = r1;
                bf[call * 2 + 1][0] = r2; bf[call * 2 + 1][1] = r3;
            }
            #pragma unroll
            for (int mi = 0; mi < 4; mi++)
                #pragma unroll
                for (int ni = 0; ni < 4; ni++)
                    asm volatile("mma.sync.aligned.m16n8k16.row.col.f32.bf16.bf16.f32 "
                        "{%0,%1,%2,%3}, {%4,%5,%6,%7}, {%8,%9}, {%0,%1,%2,%3};\n"
                        : "+f"(acc[mi][ni][0]), "+f"(acc[mi][ni][1]),
                          "+f"(acc[mi][ni][2]), "+f"(acc[mi][ni][3])
                        : "r"(a[mi][0]), "r"(a[mi][1]), "r"(a[mi][2]), "r"(a[mi][3]),
                          "r"(bf[ni][0]), "r"(bf[ni][1]));
        }
        __syncthreads();
    }

    float* C = g_sim + (size_t)bz * NN * NN;
    #pragma unroll
    for (int mi = 0; mi < 4; mi++) {
        int r = rowBase + warp_m * 64 + mi * 16 + (lane >> 2);
        #pragma unroll
        for (int ni = 0; ni < 4; ni++) {
            int c = colBase + warp_n * 32 + ni * 8 + (lane & 3) * 2;
            *(float2*)(C + (size_t)r * NN + c) = make_float2(acc[mi][ni][0], acc[mi][ni][1]);
            *(float2*)(C + (size_t)(r + 8) * NN + c) = make_float2(acc[mi][ni][2], acc[mi][ni][3]);
        }
    }
}

// =========================================================================
// K3: prepass — normalize row, zero diag, select top-12 candidates.
// =========================================================================
__global__ __launch_bounds__(256) void k_topk_node() {
    int bn = blockIdx.x;
    int b = bn >> 10, n = bn & 1023;
    __shared__ float vals[NN];
    __shared__ float rv[256];
    __shared__ int   ri[256];
    int t = threadIdx.x;
    float invn = g_inv_node_f[bn];
    const float* row = g_sim + (size_t)b * NN * NN + (size_t)n * NN;
    for (int m = t; m < NN; m += 256) {
        vals[m] = (m == n) ? 0.f : row[m] * invn * g_inv_node_f[b * NN + m];
    }
    __syncthreads();
    for (int k = 0; k < KCAND; k++) {
        float bv = NEG_INF; int bi = 0;
        #pragma unroll
        for (int j = 0; j < 4; j++) {
            int m = t + j * 256;
            float v = vals[m];
            if (v > bv) { bv = v; bi = m; }
        }
        rv[t] = bv; ri[t] = bi;
        __syncthreads();
        if (t < 32) {
            float v = rv[t]; int i = ri[t];
            #pragma unroll
            for (int j = 1; j < 8; j++) {
                float v2 = rv[t + j * 32]; int i2 = ri[t + j * 32];
                if (v2 > v || (v2 == v && i2 < i)) { v = v2; i = i2; }
            }
            #pragma unroll
            for (int o = 16; o; o >>= 1) {
                float v2 = __shfl_xor_sync(0xffffffffu, v, o);
                int   i2 = __shfl_xor_sync(0xffffffffu, i, o);
                if (v2 > v || (v2 == v && i2 < i)) { v = v2; i = i2; }
            }
            if (t == 0) {
                g_cand[bn * KCAND + k] = i;
                vals[i] = NEG_INF;
            }
        }
        __syncthreads();
    }
}

// =========================================================================
// K4: exact node re-rank over 12 candidates -> top-8; exact token cosine
// over 336 -> top-8; fused linear -> out[:, :, 42:50, :].
// =========================================================================
__global__ __launch_bounds__(256) void k_tok(const float* __restrict__ h,
                                             const float* __restrict__ W,
                                             const float* __restrict__ bias,
                                             const float* __restrict__ ntok,
                                             float* __restrict__ out) {
    extern __shared__ char dynv[];
    double* ssim = (double*)dynv;                 // 336
    double* rvd  = ssim + 336;                    // 256
    double* ex12 = rvd + 256;                     // 12
    float*  s_big = (float*)(ex12 + 12);          // 16128 (flat_n, reused as W)
    float*  stok  = s_big + 16128;                // 8*96
    float*  sq    = stok + KTOK * DD;             // 96
    int*    ri    = (int*)(sq + DD);              // 256
    int*    scand = ri + 256;                     // 12
    int*    snode = scand + KCAND;                // 8
    int*    cm    = snode + KNODE;                // 8
    int*    cp    = cm + KTOK;                    // 8

    int bn = blockIdx.x;
    int b = bn >> 10;
    int t = threadIdx.x, warp = t >> 5, lane = t & 31;

    if (t < DD) sq[t] = h[((size_t)bn * PP + (PP - 1)) * (size_t)DD + t];
    if (t < KCAND) scand[t] = g_cand[bn * KCAND + t];
    const float* fn = h + (size_t)bn * PD;
    for (int i = t; i < PD; i += 256) s_big[i] = fn[i];
    __syncthreads();

    // ---- exact node sims for 12 candidates ----
    for (int c = warp; c < KCAND; c += 8) {
        int m = scand[c];
        const float* fm = h + (size_t)(b * NN + m) * PD;
        float hi = 0.f, lo = 0.f;
        for (int i = lane; i < PD; i += 32) dot2_step(s_big[i], fm[i], hi, lo);
        double v = (double)hi + (double)lo;
        #pragma unroll
        for (int o = 16; o; o >>= 1) v += __shfl_xor_sync(0xffffffffu, v, o);
        if (lane == 0) ex12[c] = v * g_inv_node_d[bn] * g_inv_node_d[b * NN + m];
    }
    __syncthreads();

    if (t == 0) {
        unsigned used = 0;
        for (int k = 0; k < KNODE; k++) {
            int best = -1;
            for (int j = 0; j < KCAND; j++) {
                if (used & (1u << j)) continue;
                if (best < 0 || ex12[j] > ex12[best] ||
                    (ex12[j] == ex12[best] && scand[j] < scand[best])) best = j;
            }
            used |= (1u << best);
            snode[k] = scand[best];
        }
    }
    __syncthreads();

    // reuse s_big for W (transposed-padded): sW[e*97+d]
    for (int i = t; i < DD * DD; i += 256) {
        int e = i / DD, d = i - e * DD;
        s_big[e * 97 + d] = W[i];
    }

    // ---- exact token sims for 336 candidates ----
    double qinv = g_inv_tok_d[bn * PP + PP - 1];
    for (int c = warp; c < KNODE * PP; c += 8) {
        int kn = c / PP, p = c - kn * PP;
        int m = snode[kn];
        const float* tp = h + (((size_t)(b * NN + m)) * PP + p) * (size_t)DD;
        float hi = 0.f, lo = 0.f;
        dot2_step(tp[lane],      sq[lane],      hi, lo);
        dot2_step(tp[lane + 32], sq[lane + 32], hi, lo);
        dot2_step(tp[lane + 64], sq[lane + 64], hi, lo);
        double v = (double)hi + (double)lo;
        #pragma unroll
        for (int o = 16; o; o >>= 1) v += __shfl_xor_sync(0xffffffffu, v, o);
        if (lane == 0) ssim[c] = v * qinv * g_inv_tok_d[(b * NN + m) * PP + p];
    }
    __syncthreads();

    // ---- exact top-8 of 336 ----
    for (int k = 0; k < KTOK; k++) {
        double bv = NEG_INF_D; int bi = 0;
        for (int c = t; c < KNODE * PP; c += 256) {
            double v = ssim[c];
            if (v > bv) { bv = v; bi = c; }
        }
        rvd[t] = bv; ri[t] = bi;
        __syncthreads();
        if (t < 32) {
            double v = rvd[t]; int i = ri[t];
            #pragma unroll
            for (int j = 1; j < 8; j++) {
                double v2 = rvd[t + j * 32]; int i2 = ri[t + j * 32];
                if (v2 > v || (v2 == v && i2 < i)) { v = v2; i = i2; }
            }
            #pragma unroll
            for (int o = 16; o; o >>= 1) {
                double v2 = __shfl_xor_sync(0xffffffffu, v, o);
                int    i2 = __shfl_xor_sync(0xffffffffu, i, o);
                if (v2 > v || (v2 == v && i2 < i)) { v = v2; i = i2; }
            }
            if (t == 0) {
                int c = i; int kn = c / PP, p = c - kn * PP;
                cm[k] = snode[kn]; cp[k] = p;
                ssim[c] = NEG_INF_D;
            }
        }
        __syncthreads();
    }

    for (int i = t; i < KTOK * DD; i += 256) {
        int k = i / DD, d = i - k * DD;
        stok[k * DD + d] = h[(((size_t)(b * NN + cm[k])) * PP + cp[k]) * (size_t)DD + d];
    }
    __syncthreads();

    float nt = ntok[0];
    for (int o = t; o < KTOK * DD; o += 256) {
        int k = o / DD, e = o - k * DD;
        float acc = bias[e] + nt;
        #pragma unroll 8
        for (int d = 0; d < DD; d++) acc += stok[k * DD + d] * s_big[e * 97 + d];
        out[(((size_t)bn) * POUT + PP + k) * (size_t)DD + e] = acc;
    }
}

// =========================================================================
// K5: hf = h @ W^T + b -> out[:, :, 0:42, :].
// =========================================================================
__global__ __launch_bounds__(256) void k_hf(const float* __restrict__ h,
                                            const float* __restrict__ W,
                                            const float* __restrict__ bias,
                                            float* __restrict__ out) {
    extern __shared__ float dyn[];
    float* sXT = dyn;                 // [DD][65]
    float* sWT = dyn + DD * 65;       // [DD][97]

    int r0 = blockIdx.x * 64;
    int t = threadIdx.x;

    const float* Xbase = h + (size_t)r0 * DD;
    for (int i = t; i < 64 * DD; i += 256) {
        int r = i / DD, d = i - r * DD;
        sXT[d * 65 + r] = Xbase[i];
    }
    for (int i = t; i < DD * DD; i += 256) {
        int e = i / DD, d = i - e * DD;
        sWT[d * 97 + e] = W[i];
    }
    __syncthreads();

    int tx = t & 15, ty = t >> 4;
    float acc[4][6];
    #pragma unroll
    for (int i = 0; i < 4; i++)
        #pragma unroll
        for (int j = 0; j < 6; j++) acc[i][j] = bias[tx * 6 + j];

    #pragma unroll 4
    for (int d = 0; d < DD; d++) {
        float x[4], w[6];
        #pragma unroll
        for (int i = 0; i < 4; i++) x[i] = sXT[d * 65 + ty * 4 + i];
        #pragma unroll
        for (int j = 0; j < 6; j++) w[j] = sWT[d * 97 + tx * 6 + j];
        #pragma unroll
        for (int i = 0; i < 4; i++)
            #pragma unroll
            for (int j = 0; j < 6; j++) acc[i][j] += x[i] * w[j];
    }

    #pragma unroll
    for (int i = 0; i < 4; i++) {
        int r = r0 + ty * 4 + i;
        int bn = r / PP, p = r - bn * PP;
        float* orow = out + (((size_t)bn) * POUT + p) * (size_t)DD + tx * 6;
        #pragma unroll
        for (int j = 0; j < 6; j++) orow[j] = acc[i][j];
    }
}

// =========================================================================
extern "C" void kernel_launch(void* const* d_in, const int* in_sizes, int n_in,
                              void* d_out, int out_size) {
    const float* h    = (const float*)d_in[0];
    const float* W    = (const float*)d_in[1];
    const float* bias = (const float*)d_in[2];
    const float* ntok = (const float*)d_in[3];
    float* out = (float*)d_out;

    k_conv<<<(BB * NN * PD) / (256 * 4), 256>>>(h);
    k_norms<<<BB * NN, 128>>>(h);

    cudaFuncSetAttribute(k_sim_mma, cudaFuncAttributeMaxDynamicSharedMemorySize, 65536);
    dim3 g2(NN / 128, NN / 128, BB);
    k_sim_mma<<<g2, 256, 65536>>>();

    k_topk_node<<<BB * NN, 256>>>();

    size_t tok_smem = (336 + 256 + 12) * sizeof(double) +
                      (16128 + KTOK * DD + DD) * sizeof(float) +
                      (256 + KCAND + KNODE + KTOK + KTOK) * sizeof(int) + 64;
    cudaFuncSetAttribute(k_tok, cudaFuncAttributeMaxDynamicSharedMemorySize, (int)tok_smem);
    k_tok<<<BB * NN, 256, tok_smem>>>(h, W, bias, ntok, out);

    size_t hf_smem = (size_t)(DD * 65 + DD * 97) * sizeof(float);
    cudaFuncSetAttribute(k_hf, cudaFuncAttributeMaxDynamicSharedMemorySize, (int)hf_smem);
    k_hf<<<(BB * NN * PP) / 64, 256, hf_smem>>>(h, W, bias, out);
}

// round 5
// speedup vs baseline: 2.6748x; 1.9142x over previous
#include <cuda_runtime.h>
#include <cuda_bf16.h>
#include <cstdint>
#include <math.h>

#define BB 4
#define NN 1024
#define PP 42
#define DD 96
#define PD 4032          // PP*DD
#define KNODE 8
#define KCAND 12         // prepass candidates (margin over 8)
#define KTOK 8
#define POUT 50          // PP + KTOK
#define EPSD 1e-7

#define NEG_INF __int_as_float(0xff800000)
#define NEG_INF_D (-1.0e300)

// ---------------- scratch (device globals; no allocation) ----------------
__device__ float  g_sim[BB * NN * NN];        // prepass dots (fp32 out of mma)
__device__ __align__(16) __nv_bfloat16 g_hbf[BB * NN * PD];  // bf16 copy of h
__device__ double g_inv_node_d[BB * NN];
__device__ float  g_inv_node_f[BB * NN];
__device__ double g_inv_tok_d[BB * NN * PP];
__device__ int    g_cand[BB * NN * KCAND];    // prepass top-12
__device__ int    g_node[BB * NN * KNODE];    // exact top-8 nodes

// ---------------- compensated arithmetic helpers --------------------------
__device__ __forceinline__ void two_sum(float a, float b, float& s, float& e) {
    s = a + b;
    float z = s - a;
    e = (a - (s - z)) + (b - z);
}
__device__ __forceinline__ void dot2_step(float a, float b, float& hi, float& lo) {
    float p = a * b;
    float ep = fmaf(a, b, -p);
    float s, e;
    two_sum(hi, p, s, e);
    hi = s;
    lo += e + ep;
}

__device__ __forceinline__ void cp16(uint32_t s, const void* g) {
    asm volatile("cp.async.cg.shared.global [%0], [%1], 16;\n" :: "r"(s), "l"(g));
}

// =========================================================================
// K0: h (fp32) -> g_hbf (bf16).
// =========================================================================
__global__ __launch_bounds__(256) void k_conv(const float* __restrict__ h) {
    size_t i = ((size_t)blockIdx.x * 256 + threadIdx.x) * 4;
    float4 v = *(const float4*)(h + i);
    __nv_bfloat162 lo = __floats2bfloat162_rn(v.x, v.y);
    __nv_bfloat162 hi = __floats2bfloat162_rn(v.z, v.w);
    uint2 pk;
    pk.x = *(uint32_t*)&lo;
    pk.y = *(uint32_t*)&hi;
    *(uint2*)(&g_hbf[i]) = pk;
}

// =========================================================================
// K1: exact token norms + node norms (compensated fp32 -> fp64).
// =========================================================================
__global__ __launch_bounds__(128) void k_norms(const float* __restrict__ h) {
    int bn = blockIdx.x;
    const float* base = h + (size_t)bn * PD;
    __shared__ double s_node[4];
    int warp = threadIdx.x >> 5, lane = threadIdx.x & 31;
    double nodesum = 0.0;
    for (int p = warp; p < PP; p += 4) {
        const float* tp = base + p * DD;
        float hi = 0.f, lo = 0.f;
        float v0 = tp[lane], v1 = tp[lane + 32], v2 = tp[lane + 64];
        dot2_step(v0, v0, hi, lo);
        dot2_step(v1, v1, hi, lo);
        dot2_step(v2, v2, hi, lo);
        double s = (double)hi + (double)lo;
        #pragma unroll
        for (int o = 16; o; o >>= 1) s += __shfl_xor_sync(0xffffffffu, s, o);
        if (lane == 0) g_inv_tok_d[bn * PP + p] = 1.0 / (sqrt(s) + EPSD);
        nodesum += s;
    }
    if (lane == 0) s_node[warp] = nodesum;
    __syncthreads();
    if (threadIdx.x == 0) {
        double t = s_node[0] + s_node[1] + s_node[2] + s_node[3];
        double inv = 1.0 / (sqrt(t) + EPSD);
        g_inv_node_d[bn] = inv;
        g_inv_node_f[bn] = (float)inv;
    }
}

// =========================================================================
// K2: bf16 tensor-core prepass GEMM: g_sim = flat_bf16 @ flat_bf16^T.
// (proven correct in R4 — unchanged)
// =========================================================================
__global__ void __launch_bounds__(256, 2) k_sim_mma() {
    extern __shared__ __align__(16) unsigned char smraw[];
    const int t = threadIdx.x;
    const int lane = t & 31, warp = t >> 5;
    const int warp_m = warp >> 2, warp_n = warp & 3;
    const int bz = blockIdx.z;
    const int rowBase = blockIdx.y * 128, colBase = blockIdx.x * 128;
    const __nv_bfloat16* base = g_hbf + (size_t)bz * NN * PD;
    uint32_t s0 = (uint32_t)__cvta_generic_to_shared(smraw);

    float acc[4][4][4];
    #pragma unroll
    for (int i = 0; i < 4; i++)
        #pragma unroll
        for (int j = 0; j < 4; j++)
            #pragma unroll
            for (int q = 0; q < 4; q++) acc[i][j][q] = 0.f;

    auto issue = [&](int it, int buf) {
        int k0 = it * 64;
        uint32_t sbuf = s0 + buf * 32768;
        #pragma unroll
        for (int i = 0; i < 4; i++) {
            int u = t + 256 * i;
            int r = u >> 3, c = u & 7;
            uint32_t soff = r * 128 + ((c ^ (r & 7)) << 4);
            cp16(sbuf + soff, base + (size_t)(rowBase + r) * PD + k0 + c * 8);
            cp16(sbuf + 16384 + soff, base + (size_t)(colBase + r) * PD + k0 + c * 8);
        }
        asm volatile("cp.async.commit_group;\n");
    };

    issue(0, 0);
    for (int it = 0; it < 63; it++) {
        if (it < 62) {
            issue(it + 1, (it + 1) & 1);
            asm volatile("cp.async.wait_group 1;\n");
        } else {
            asm volatile("cp.async.wait_group 0;\n");
        }
        __syncthreads();
        uint32_t sA = s0 + (it & 1) * 32768;
        uint32_t sB = sA + 16384;
        #pragma unroll
        for (int kk = 0; kk < 4; kk++) {
            uint32_t a[4][4], bf[4][2];
            #pragma unroll
            for (int mi = 0; mi < 4; mi++) {
                int row = warp_m * 64 + mi * 16 + ((lane >> 3) & 1) * 8 + (lane & 7);
                int ch = kk * 2 + (lane >> 4);
                uint32_t addr = sA + row * 128 + ((ch ^ (row & 7)) << 4);
                asm volatile("ldmatrix.sync.aligned.m8n8.x4.shared.b16 {%0,%1,%2,%3}, [%4];\n"
                    : "=r"(a[mi][0]), "=r"(a[mi][1]), "=r"(a[mi][2]), "=r"(a[mi][3]) : "r"(addr));
            }
            #pragma unroll
            for (int call = 0; call < 2; call++) {
                int row = warp_n * 32 + call * 16 + ((lane >> 4) & 1) * 8 + (lane & 7);
                int ch = kk * 2 + ((lane >> 3) & 1);
                uint32_t addr = sB + row * 128 + ((ch ^ (row & 7)) << 4);
                uint32_t r0, r1, r2, r3;
                asm volatile("ldmatrix.sync.aligned.m8n8.x4.shared.b16 {%0,%1,%2,%3}, [%4];\n"
                    : "=r"(r0), "=r"(r1), "=r"(r2), "=r"(r3) : "r"(addr));
                bf[call * 2][0] = r0; bf[call * 2][1] = r1;
                bf[call * 2 + 1][0] = r2; bf[call * 2 + 1][1] = r3;
            }
            #pragma unroll
            for (int mi = 0; mi < 4; mi++)
                #pragma unroll
                for (int ni = 0; ni < 4; ni++)
                    asm volatile("mma.sync.aligned.m16n8k16.row.col.f32.bf16.bf16.f32 "
                        "{%0,%1,%2,%3}, {%4,%5,%6,%7}, {%8,%9}, {%0,%1,%2,%3};\n"
                        : "+f"(acc[mi][ni][0]), "+f"(acc[mi][ni][1]),
                          "+f"(acc[mi][ni][2]), "+f"(acc[mi][ni][3])
                        : "r"(a[mi][0]), "r"(a[mi][1]), "r"(a[mi][2]), "r"(a[mi][3]),
                          "r"(bf[ni][0]), "r"(bf[ni][1]));
        }
        __syncthreads();
    }

    float* C = g_sim + (size_t)bz * NN * NN;
    #pragma unroll
    for (int mi = 0; mi < 4; mi++) {
        int r = rowBase + warp_m * 64 + mi * 16 + (lane >> 2);
        #pragma unroll
        for (int ni = 0; ni < 4; ni++) {
            int c = colBase + warp_n * 32 + ni * 8 + (lane & 3) * 2;
            *(float2*)(C + (size_t)r * NN + c) = make_float2(acc[mi][ni][0], acc[mi][ni][1]);
            *(float2*)(C + (size_t)(r + 8) * NN + c) = make_float2(acc[mi][ni][2], acc[mi][ni][3]);
        }
    }
}

// =========================================================================
// K3: prepass — normalize row, zero diag, select top-12 candidates.
// =========================================================================
__global__ __launch_bounds__(256) void k_topk_node() {
    int bn = blockIdx.x;
    int b = bn >> 10, n = bn & 1023;
    __shared__ float vals[NN];
    __shared__ float rv[256];
    __shared__ int   ri[256];
    int t = threadIdx.x;
    float invn = g_inv_node_f[bn];
    const float* row = g_sim + (size_t)b * NN * NN + (size_t)n * NN;
    for (int m = t; m < NN; m += 256) {
        vals[m] = (m == n) ? 0.f : row[m] * invn * g_inv_node_f[b * NN + m];
    }
    __syncthreads();
    for (int k = 0; k < KCAND; k++) {
        float bv = NEG_INF; int bi = 0;
        #pragma unroll
        for (int j = 0; j < 4; j++) {
            int m = t + j * 256;
            float v = vals[m];
            if (v > bv) { bv = v; bi = m; }
        }
        rv[t] = bv; ri[t] = bi;
        __syncthreads();
        if (t < 32) {
            float v = rv[t]; int i = ri[t];
            #pragma unroll
            for (int j = 1; j < 8; j++) {
                float v2 = rv[t + j * 32]; int i2 = ri[t + j * 32];
                if (v2 > v || (v2 == v && i2 < i)) { v = v2; i = i2; }
            }
            #pragma unroll
            for (int o = 16; o; o >>= 1) {
                float v2 = __shfl_xor_sync(0xffffffffu, v, o);
                int   i2 = __shfl_xor_sync(0xffffffffu, i, o);
                if (v2 > v || (v2 == v && i2 < i)) { v = v2; i = i2; }
            }
            if (t == 0) {
                g_cand[bn * KCAND + k] = i;
                vals[i] = NEG_INF;
            }
        }
        __syncthreads();
    }
}

// =========================================================================
// K3b (NEW): exact node re-rank.  One block per bn, 384 threads = 12 warps,
// one warp per candidate.  float4 loads, 4 independent compensated
// accumulators (MLP).  Ends with thread-0 top-8-of-12 -> g_node.
// =========================================================================
__global__ __launch_bounds__(384) void k_rerank(const float* __restrict__ h) {
    __shared__ __align__(16) float sQ[PD];       // query row, 16 KB
    __shared__ double exd[KCAND];
    __shared__ int    scnd[KCAND];

    int bn = blockIdx.x;
    int b = bn >> 10;
    int t = threadIdx.x, warp = t >> 5, lane = t & 31;

    const float4* q4 = (const float4*)(h + (size_t)bn * PD);
    float4* sQ4 = (float4*)sQ;
    for (int i = t; i < PD / 4; i += 384) sQ4[i] = q4[i];
    __syncthreads();

    // warp w handles candidate w
    int m = __shfl_sync(0xffffffffu, (lane == 0) ? g_cand[bn * KCAND + warp] : 0, 0);
    const float4* f4 = (const float4*)(h + (size_t)(b * NN + m) * PD);

    float hx = 0.f, lx = 0.f, hy = 0.f, ly = 0.f;
    float hz = 0.f, lz = 0.f, hw = 0.f, lw = 0.f;
    #pragma unroll 4
    for (int j = 0; j < 31; j++) {
        int i4 = j * 32 + lane;
        float4 a = sQ4[i4];
        float4 c = f4[i4];
        dot2_step(a.x, c.x, hx, lx);
        dot2_step(a.y, c.y, hy, ly);
        dot2_step(a.z, c.z, hz, lz);
        dot2_step(a.w, c.w, hw, lw);
    }
    if (lane < 16) {                             // tail: float4 992..1007
        int i4 = 992 + lane;
        float4 a = sQ4[i4];
        float4 c = f4[i4];
        dot2_step(a.x, c.x, hx, lx);
        dot2_step(a.y, c.y, hy, ly);
        dot2_step(a.z, c.z, hz, lz);
        dot2_step(a.w, c.w, hw, lw);
    }
    double v = ((double)hx + lx) + ((double)hy + ly) +
               ((double)hz + lz) + ((double)hw + lw);
    #pragma unroll
    for (int o = 16; o; o >>= 1) v += __shfl_xor_sync(0xffffffffu, v, o);
    if (lane == 0) {
        exd[warp] = v * g_inv_node_d[bn] * g_inv_node_d[b * NN + m];
        scnd[warp] = m;
    }
    __syncthreads();

    if (t == 0) {
        unsigned used = 0;
        for (int k = 0; k < KNODE; k++) {
            int best = -1;
            for (int j = 0; j < KCAND; j++) {
                if (used & (1u << j)) continue;
                if (best < 0 || exd[j] > exd[best] ||
                    (exd[j] == exd[best] && scnd[j] < scnd[best])) best = j;
            }
            used |= (1u << best);
            g_node[bn * KNODE + k] = scnd[best];
        }
    }
}

// =========================================================================
// K4: token cosine over 336 candidates (per-THREAD, float4, 4 acc pairs),
// top-8, fused linear -> out[:, :, 42:50, :].  One block per bn, 256 thr.
// =========================================================================
__global__ __launch_bounds__(256) void k_tok(const float* __restrict__ h,
                                             const float* __restrict__ W,
                                             const float* __restrict__ bias,
                                             const float* __restrict__ ntok,
                                             float* __restrict__ out) {
    extern __shared__ char dynv[];
    double* ssim = (double*)dynv;                 // 336
    double* rvd  = ssim + 336;                    // 256
    float*  sq   = (float*)(rvd + 256);           // 96 (16B aligned)
    float*  stok = sq + DD;                       // 768
    float*  sW   = stok + KTOK * DD;              // 96*97
    int*    ri   = (int*)(sW + DD * 97);          // 256
    int*    snode= ri + 256;                      // 8
    int*    cm   = snode + KNODE;                 // 8
    int*    cp   = cm + KTOK;                     // 8

    int bn = blockIdx.x;
    int b = bn >> 10;
    int t = threadIdx.x;

    // stage query token (float4), node list, W (transposed-padded)
    if (t < DD / 4)
        ((float4*)sq)[t] = ((const float4*)(h + ((size_t)bn * PP + (PP - 1)) * DD))[t];
    if (t < KNODE) snode[t] = g_node[bn * KNODE + t];
    for (int i = t; i < DD * DD; i += 256) {
        int e = i / DD, d = i - e * DD;
        sW[e * 97 + d] = W[i];
    }
    __syncthreads();

    // ---- per-thread exact token sims (336 candidates) ----
    double qinv = g_inv_tok_d[bn * PP + PP - 1];
    const float4* sq4 = (const float4*)sq;
    for (int c = t; c < KNODE * PP; c += 256) {
        int kn = c / PP, p = c - kn * PP;
        int m = snode[kn];
        const float4* tp4 = (const float4*)(h + (((size_t)(b * NN + m)) * PP + p) * DD);
        float hx = 0.f, lx = 0.f, hy = 0.f, ly = 0.f;
        float hz = 0.f, lz = 0.f, hw = 0.f, lw = 0.f;
        #pragma unroll
        for (int j = 0; j < DD / 4; j++) {
            float4 a = sq4[j];
            float4 f = tp4[j];
            dot2_step(a.x, f.x, hx, lx);
            dot2_step(a.y, f.y, hy, ly);
            dot2_step(a.z, f.z, hz, lz);
            dot2_step(a.w, f.w, hw, lw);
        }
        double v = ((double)hx + lx) + ((double)hy + ly) +
                   ((double)hz + lz) + ((double)hw + lw);
        ssim[c] = v * qinv * g_inv_tok_d[(b * NN + m) * PP + p];
    }
    __syncthreads();

    // ---- exact top-8 of 336 (value desc, tie -> lower candidate index) ----
    for (int k = 0; k < KTOK; k++) {
        double bv = NEG_INF_D; int bi = 0;
        for (int c = t; c < KNODE * PP; c += 256) {
            double v = ssim[c];
            if (v > bv) { bv = v; bi = c; }
        }
        rvd[t] = bv; ri[t] = bi;
        __syncthreads();
        if (t < 32) {
            double v = rvd[t]; int i = ri[t];
            #pragma unroll
            for (int j = 1; j < 8; j++) {
                double v2 = rvd[t + j * 32]; int i2 = ri[t + j * 32];
                if (v2 > v || (v2 == v && i2 < i)) { v = v2; i = i2; }
            }
            #pragma unroll
            for (int o = 16; o; o >>= 1) {
                double v2 = __shfl_xor_sync(0xffffffffu, v, o);
                int    i2 = __shfl_xor_sync(0xffffffffu, i, o);
                if (v2 > v || (v2 == v && i2 < i)) { v = v2; i = i2; }
            }
            if (t == 0) {
                int c = i; int kn = c / PP, p = c - kn * PP;
                cm[k] = snode[kn]; cp[k] = p;
                ssim[c] = NEG_INF_D;
            }
        }
        __syncthreads();
    }

    // gather selected tokens (float4)
    if (t < KTOK * DD / 4) {
        int k = t / (DD / 4), j = t - k * (DD / 4);
        ((float4*)stok)[t] =
            ((const float4*)(h + (((size_t)(b * NN + cm[k])) * PP + cp[k]) * DD))[j];
    }
    __syncthreads();

    float nt = ntok[0];
    for (int o = t; o < KTOK * DD; o += 256) {
        int k = o / DD, e = o - k * DD;
        float acc = bias[e] + nt;
        #pragma unroll 8
        for (int d = 0; d < DD; d++) acc += stok[k * DD + d] * sW[e * 97 + d];
        out[(((size_t)bn) * POUT + PP + k) * (size_t)DD + e] = acc;
    }
}

// =========================================================================
// K5: hf = h @ W^T + b -> out[:, :, 0:42, :].  Vectorized smem reads:
// sXT stride 68 (LDS.128 for 4 rows), sWT stride 98 (LDS.64 x3 for 6 cols).
// =========================================================================
__global__ __launch_bounds__(256) void k_hf(const float* __restrict__ h,
                                            const float* __restrict__ W,
                                            const float* __restrict__ bias,
                                            float* __restrict__ out) {
    extern __shared__ __align__(16) float dyn[];
    float* sXT = dyn;                 // [DD][68]
    float* sWT = dyn + DD * 68;       // [DD][98]

    int r0 = blockIdx.x * 64;
    int t = threadIdx.x;

    const float* Xbase = h + (size_t)r0 * DD;
    for (int i = t; i < 64 * DD; i += 256) {
        int r = i / DD, d = i - r * DD;
        sXT[d * 68 + r] = Xbase[i];
    }
    for (int i = t; i < DD * DD; i += 256) {
        int e = i / DD, d = i - e * DD;
        sWT[d * 98 + e] = W[i];
    }
    __syncthreads();

    int tx = t & 15, ty = t >> 4;
    float acc[4][6];
    #pragma unroll
    for (int i = 0; i < 4; i++)
        #pragma unroll
        for (int j = 0; j < 6; j++) acc[i][j] = bias[tx * 6 + j];

    #pragma unroll 4
    for (int d = 0; d < DD; d++) {
        float4 xv = *(const float4*)(sXT + d * 68 + ty * 4);
        float2 w0 = *(const float2*)(sWT + d * 98 + tx * 6);
        float2 w1 = *(const float2*)(sWT + d * 98 + tx * 6 + 2);
        float2 w2 = *(const float2*)(sWT + d * 98 + tx * 6 + 4);
        float x[4] = {xv.x, xv.y, xv.z, xv.w};
        float w[6] = {w0.x, w0.y, w1.x, w1.y, w2.x, w2.y};
        #pragma unroll
        for (int i = 0; i < 4; i++)
            #pragma unroll
            for (int j = 0; j < 6; j++) acc[i][j] += x[i] * w[j];
    }

    #pragma unroll
    for (int i = 0; i < 4; i++) {
        int r = r0 + ty * 4 + i;
        int bn = r / PP, p = r - bn * PP;
        float* orow = out + (((size_t)bn) * POUT + p) * (size_t)DD + tx * 6;
        #pragma unroll
        for (int j = 0; j < 6; j++) orow[j] = acc[i][j];
    }
}

// =========================================================================
extern "C" void kernel_launch(void* const* d_in, const int* in_sizes, int n_in,
                              void* d_out, int out_size) {
    const float* h    = (const float*)d_in[0];
    const float* W    = (const float*)d_in[1];
    const float* bias = (const float*)d_in[2];
    const float* ntok = (const float*)d_in[3];
    float* out = (float*)d_out;

    k_conv<<<(BB * NN * PD) / (256 * 4), 256>>>(h);
    k_norms<<<BB * NN, 128>>>(h);

    cudaFuncSetAttribute(k_sim_mma, cudaFuncAttributeMaxDynamicSharedMemorySize, 65536);
    dim3 g2(NN / 128, NN / 128, BB);
    k_sim_mma<<<g2, 256, 65536>>>();

    k_topk_node<<<BB * NN, 256>>>();

    k_rerank<<<BB * NN, 384>>>(h);

    size_t tok_smem = (336 + 256) * sizeof(double) +
                      (DD + KTOK * DD + DD * 97) * sizeof(float) +
                      (256 + KNODE + KTOK + KTOK) * sizeof(int);
    cudaFuncSetAttribute(k_tok, cudaFuncAttributeMaxDynamicSharedMemorySize, (int)tok_smem);
    k_tok<<<BB * NN, 256, tok_smem>>>(h, W, bias, ntok, out);

    size_t hf_smem = (size_t)(DD * 68 + DD * 98) * sizeof(float);
    cudaFuncSetAttribute(k_hf, cudaFuncAttributeMaxDynamicSharedMemorySize, (int)hf_smem);
    k_hf<<<(BB * NN * PP) / 64, 256, hf_smem>>>(h, W, bias, out);
}

// round 6
// speedup vs baseline: 2.6947x; 1.0074x over previous
#include <cuda_runtime.h>
#include <cuda_bf16.h>
#include <cstdint>
#include <math.h>

#define BB 4
#define NN 1024
#define PP 42
#define DD 96
#define PD 4032          // PP*DD
#define KNODE 8
#define KCAND 12         // prepass candidates (margin over 8)
#define KTOK 8
#define POUT 50          // PP + KTOK
#define EPSD 1e-7

#define NEG_INF __int_as_float(0xff800000)
#define NEG_INF_D (-1.0e300)

// ---------------- scratch (device globals; no allocation) ----------------
__device__ float  g_sim[BB * NN * NN];        // prepass dots (fp32 out of mma)
__device__ __align__(16) __nv_bfloat16 g_hbf[BB * NN * PD];  // bf16 copy of h
__device__ double g_inv_node_d[BB * NN];
__device__ float  g_inv_node_f[BB * NN];
__device__ double g_inv_tok_d[BB * NN * PP];
__device__ int    g_cand[BB * NN * KCAND];    // prepass top-12
__device__ int    g_node[BB * NN * KNODE];    // exact top-8 nodes

// ---------------- compensated arithmetic helpers --------------------------
__device__ __forceinline__ void two_sum(float a, float b, float& s, float& e) {
    s = a + b;
    float z = s - a;
    e = (a - (s - z)) + (b - z);
}
__device__ __forceinline__ void dot2_step(float a, float b, float& hi, float& lo) {
    float p = a * b;
    float ep = fmaf(a, b, -p);
    float s, e;
    two_sum(hi, p, s, e);
    hi = s;
    lo += e + ep;
}

__device__ __forceinline__ void cp16(uint32_t s, const void* g) {
    asm volatile("cp.async.cg.shared.global [%0], [%1], 16;\n" :: "r"(s), "l"(g));
}

// =========================================================================
// K0: h (fp32) -> g_hbf (bf16).
// =========================================================================
__global__ __launch_bounds__(256) void k_conv(const float* __restrict__ h) {
    size_t i = ((size_t)blockIdx.x * 256 + threadIdx.x) * 4;
    float4 v = *(const float4*)(h + i);
    __nv_bfloat162 lo = __floats2bfloat162_rn(v.x, v.y);
    __nv_bfloat162 hi = __floats2bfloat162_rn(v.z, v.w);
    uint2 pk;
    pk.x = *(uint32_t*)&lo;
    pk.y = *(uint32_t*)&hi;
    *(uint2*)(&g_hbf[i]) = pk;
}

// =========================================================================
// K1: exact token norms + node norms (compensated fp32 -> fp64).
// =========================================================================
__global__ __launch_bounds__(128) void k_norms(const float* __restrict__ h) {
    int bn = blockIdx.x;
    const float* base = h + (size_t)bn * PD;
    __shared__ double s_node[4];
    int warp = threadIdx.x >> 5, lane = threadIdx.x & 31;
    double nodesum = 0.0;
    for (int p = warp; p < PP; p += 4) {
        const float* tp = base + p * DD;
        float hi = 0.f, lo = 0.f;
        float v0 = tp[lane], v1 = tp[lane + 32], v2 = tp[lane + 64];
        dot2_step(v0, v0, hi, lo);
        dot2_step(v1, v1, hi, lo);
        dot2_step(v2, v2, hi, lo);
        double s = (double)hi + (double)lo;
        #pragma unroll
        for (int o = 16; o; o >>= 1) s += __shfl_xor_sync(0xffffffffu, s, o);
        if (lane == 0) g_inv_tok_d[bn * PP + p] = 1.0 / (sqrt(s) + EPSD);
        nodesum += s;
    }
    if (lane == 0) s_node[warp] = nodesum;
    __syncthreads();
    if (threadIdx.x == 0) {
        double t = s_node[0] + s_node[1] + s_node[2] + s_node[3];
        double inv = 1.0 / (sqrt(t) + EPSD);
        g_inv_node_d[bn] = inv;
        g_inv_node_f[bn] = (float)inv;
    }
}

// =========================================================================
// K2: bf16 tensor-core prepass GEMM: g_sim = flat_bf16 @ flat_bf16^T.
// SYMMETRIC: only tiles with rowTile <= colTile are computed; off-diagonal
// CTAs mirror-write the transposed tile.  Work x0.5625.
// =========================================================================
__global__ void __launch_bounds__(256, 2) k_sim_mma() {
    if (blockIdx.y > blockIdx.x) return;         // lower-triangle tiles skipped
    extern __shared__ __align__(16) unsigned char smraw[];
    const int t = threadIdx.x;
    const int lane = t & 31, warp = t >> 5;
    const int warp_m = warp >> 2, warp_n = warp & 3;
    const int bz = blockIdx.z;
    const int rowBase = blockIdx.y * 128, colBase = blockIdx.x * 128;
    const __nv_bfloat16* base = g_hbf + (size_t)bz * NN * PD;
    uint32_t s0 = (uint32_t)__cvta_generic_to_shared(smraw);

    float acc[4][4][4];
    #pragma unroll
    for (int i = 0; i < 4; i++)
        #pragma unroll
        for (int j = 0; j < 4; j++)
            #pragma unroll
            for (int q = 0; q < 4; q++) acc[i][j][q] = 0.f;

    auto issue = [&](int it, int buf) {
        int k0 = it * 64;
        uint32_t sbuf = s0 + buf * 32768;
        #pragma unroll
        for (int i = 0; i < 4; i++) {
            int u = t + 256 * i;
            int r = u >> 3, c = u & 7;
            uint32_t soff = r * 128 + ((c ^ (r & 7)) << 4);
            cp16(sbuf + soff, base + (size_t)(rowBase + r) * PD + k0 + c * 8);
            cp16(sbuf + 16384 + soff, base + (size_t)(colBase + r) * PD + k0 + c * 8);
        }
        asm volatile("cp.async.commit_group;\n");
    };

    issue(0, 0);
    for (int it = 0; it < 63; it++) {
        if (it < 62) {
            issue(it + 1, (it + 1) & 1);
            asm volatile("cp.async.wait_group 1;\n");
        } else {
            asm volatile("cp.async.wait_group 0;\n");
        }
        __syncthreads();
        uint32_t sA = s0 + (it & 1) * 32768;
        uint32_t sB = sA + 16384;
        #pragma unroll
        for (int kk = 0; kk < 4; kk++) {
            uint32_t a[4][4], bf[4][2];
            #pragma unroll
            for (int mi = 0; mi < 4; mi++) {
                int row = warp_m * 64 + mi * 16 + ((lane >> 3) & 1) * 8 + (lane & 7);
                int ch = kk * 2 + (lane >> 4);
                uint32_t addr = sA + row * 128 + ((ch ^ (row & 7)) << 4);
                asm volatile("ldmatrix.sync.aligned.m8n8.x4.shared.b16 {%0,%1,%2,%3}, [%4];\n"
                    : "=r"(a[mi][0]), "=r"(a[mi][1]), "=r"(a[mi][2]), "=r"(a[mi][3]) : "r"(addr));
            }
            #pragma unroll
            for (int call = 0; call < 2; call++) {
                int row = warp_n * 32 + call * 16 + ((lane >> 4) & 1) * 8 + (lane & 7);
                int ch = kk * 2 + ((lane >> 3) & 1);
                uint32_t addr = sB + row * 128 + ((ch ^ (row & 7)) << 4);
                uint32_t r0, r1, r2, r3;
                asm volatile("ldmatrix.sync.aligned.m8n8.x4.shared.b16 {%0,%1,%2,%3}, [%4];\n"
                    : "=r"(r0), "=r"(r1), "=r"(r2), "=r"(r3) : "r"(addr));
                bf[call * 2][0] = r0; bf[call * 2][1] = r1;
                bf[call * 2 + 1][0] = r2; bf[call * 2 + 1][1] = r3;
            }
            #pragma unroll
            for (int mi = 0; mi < 4; mi++)
                #pragma unroll
                for (int ni = 0; ni < 4; ni++)
                    asm volatile("mma.sync.aligned.m16n8k16.row.col.f32.bf16.bf16.f32 "
                        "{%0,%1,%2,%3}, {%4,%5,%6,%7}, {%8,%9}, {%0,%1,%2,%3};\n"
                        : "+f"(acc[mi][ni][0]), "+f"(acc[mi][ni][1]),
                          "+f"(acc[mi][ni][2]), "+f"(acc[mi][ni][3])
                        : "r"(a[mi][0]), "r"(a[mi][1]), "r"(a[mi][2]), "r"(a[mi][3]),
                          "r"(bf[ni][0]), "r"(bf[ni][1]));
        }
        __syncthreads();
    }

    float* C = g_sim + (size_t)bz * NN * NN;
    const bool offdiag = (rowBase != colBase);
    #pragma unroll
    for (int mi = 0; mi < 4; mi++) {
        int r = rowBase + warp_m * 64 + mi * 16 + (lane >> 2);
        #pragma unroll
        for (int ni = 0; ni < 4; ni++) {
            int c = colBase + warp_n * 32 + ni * 8 + (lane & 3) * 2;
            *(float2*)(C + (size_t)r * NN + c) = make_float2(acc[mi][ni][0], acc[mi][ni][1]);
            *(float2*)(C + (size_t)(r + 8) * NN + c) = make_float2(acc[mi][ni][2], acc[mi][ni][3]);
            if (offdiag) {
                C[(size_t)c * NN + r]           = acc[mi][ni][0];
                C[(size_t)(c + 1) * NN + r]     = acc[mi][ni][1];
                C[(size_t)c * NN + r + 8]       = acc[mi][ni][2];
                C[(size_t)(c + 1) * NN + r + 8] = acc[mi][ni][3];
            }
        }
    }
}

// =========================================================================
// K3: prepass — normalize row, zero diag, select top-12 candidates.
// =========================================================================
__global__ __launch_bounds__(256) void k_topk_node() {
    int bn = blockIdx.x;
    int b = bn >> 10, n = bn & 1023;
    __shared__ float vals[NN];
    __shared__ float rv[256];
    __shared__ int   ri[256];
    int t = threadIdx.x;
    float invn = g_inv_node_f[bn];
    const float* row = g_sim + (size_t)b * NN * NN + (size_t)n * NN;
    for (int m = t; m < NN; m += 256) {
        vals[m] = (m == n) ? 0.f : row[m] * invn * g_inv_node_f[b * NN + m];
    }
    __syncthreads();
    for (int k = 0; k < KCAND; k++) {
        float bv = NEG_INF; int bi = 0;
        #pragma unroll
        for (int j = 0; j < 4; j++) {
            int m = t + j * 256;
            float v = vals[m];
            if (v > bv) { bv = v; bi = m; }
        }
        rv[t] = bv; ri[t] = bi;
        __syncthreads();
        if (t < 32) {
            float v = rv[t]; int i = ri[t];
            #pragma unroll
            for (int j = 1; j < 8; j++) {
                float v2 = rv[t + j * 32]; int i2 = ri[t + j * 32];
                if (v2 > v || (v2 == v && i2 < i)) { v = v2; i = i2; }
            }
            #pragma unroll
            for (int o = 16; o; o >>= 1) {
                float v2 = __shfl_xor_sync(0xffffffffu, v, o);
                int   i2 = __shfl_xor_sync(0xffffffffu, i, o);
                if (v2 > v || (v2 == v && i2 < i)) { v = v2; i = i2; }
            }
            if (t == 0) {
                g_cand[bn * KCAND + k] = i;
                vals[i] = NEG_INF;
            }
        }
        __syncthreads();
    }
}

// =========================================================================
// K3b: exact node re-rank.  One block per bn, 384 threads = 12 warps,
// one warp per candidate.
// =========================================================================
__global__ __launch_bounds__(384) void k_rerank(const float* __restrict__ h) {
    __shared__ __align__(16) float sQ[PD];
    __shared__ double exd[KCAND];
    __shared__ int    scnd[KCAND];

    int bn = blockIdx.x;
    int b = bn >> 10;
    int t = threadIdx.x, warp = t >> 5, lane = t & 31;

    const float4* q4 = (const float4*)(h + (size_t)bn * PD);
    float4* sQ4 = (float4*)sQ;
    for (int i = t; i < PD / 4; i += 384) sQ4[i] = q4[i];
    __syncthreads();

    int m = __shfl_sync(0xffffffffu, (lane == 0) ? g_cand[bn * KCAND + warp] : 0, 0);
    const float4* f4 = (const float4*)(h + (size_t)(b * NN + m) * PD);

    float hx = 0.f, lx = 0.f, hy = 0.f, ly = 0.f;
    float hz = 0.f, lz = 0.f, hw = 0.f, lw = 0.f;
    #pragma unroll 4
    for (int j = 0; j < 31; j++) {
        int i4 = j * 32 + lane;
        float4 a = sQ4[i4];
        float4 c = f4[i4];
        dot2_step(a.x, c.x, hx, lx);
        dot2_step(a.y, c.y, hy, ly);
        dot2_step(a.z, c.z, hz, lz);
        dot2_step(a.w, c.w, hw, lw);
    }
    if (lane < 16) {
        int i4 = 992 + lane;
        float4 a = sQ4[i4];
        float4 c = f4[i4];
        dot2_step(a.x, c.x, hx, lx);
        dot2_step(a.y, c.y, hy, ly);
        dot2_step(a.z, c.z, hz, lz);
        dot2_step(a.w, c.w, hw, lw);
    }
    double v = ((double)hx + lx) + ((double)hy + ly) +
               ((double)hz + lz) + ((double)hw + lw);
    #pragma unroll
    for (int o = 16; o; o >>= 1) v += __shfl_xor_sync(0xffffffffu, v, o);
    if (lane == 0) {
        exd[warp] = v * g_inv_node_d[bn] * g_inv_node_d[b * NN + m];
        scnd[warp] = m;
    }
    __syncthreads();

    if (t == 0) {
        unsigned used = 0;
        for (int k = 0; k < KNODE; k++) {
            int best = -1;
            for (int j = 0; j < KCAND; j++) {
                if (used & (1u << j)) continue;
                if (best < 0 || exd[j] > exd[best] ||
                    (exd[j] == exd[best] && scnd[j] < scnd[best])) best = j;
            }
            used |= (1u << best);
            g_node[bn * KNODE + k] = scnd[best];
        }
    }
}

// =========================================================================
// K4: token cosine over 336 candidates (per-thread), top-8, fused linear
// -> out[:, :, 42:50, :].
// =========================================================================
__global__ __launch_bounds__(256) void k_tok(const float* __restrict__ h,
                                             const float* __restrict__ W,
                                             const float* __restrict__ bias,
                                             const float* __restrict__ ntok,
                                             float* __restrict__ out) {
    extern __shared__ char dynv[];
    double* ssim = (double*)dynv;                 // 336
    double* rvd  = ssim + 336;                    // 256
    float*  sq   = (float*)(rvd + 256);           // 96
    float*  stok = sq + DD;                       // 768
    float*  sW   = stok + KTOK * DD;              // 96*97
    int*    ri   = (int*)(sW + DD * 97);          // 256
    int*    snode= ri + 256;                      // 8
    int*    cm   = snode + KNODE;                 // 8
    int*    cp   = cm + KTOK;                     // 8

    int bn = blockIdx.x;
    int b = bn >> 10;
    int t = threadIdx.x;

    if (t < DD / 4)
        ((float4*)sq)[t] = ((const float4*)(h + ((size_t)bn * PP + (PP - 1)) * DD))[t];
    if (t < KNODE) snode[t] = g_node[bn * KNODE + t];
    for (int i = t; i < DD * DD; i += 256) {
        int e = i / DD, d = i - e * DD;
        sW[e * 97 + d] = W[i];
    }
    __syncthreads();

    double qinv = g_inv_tok_d[bn * PP + PP - 1];
    const float4* sq4 = (const float4*)sq;
    for (int c = t; c < KNODE * PP; c += 256) {
        int kn = c / PP, p = c - kn * PP;
        int m = snode[kn];
        const float4* tp4 = (const float4*)(h + (((size_t)(b * NN + m)) * PP + p) * DD);
        float hx = 0.f, lx = 0.f, hy = 0.f, ly = 0.f;
        float hz = 0.f, lz = 0.f, hw = 0.f, lw = 0.f;
        #pragma unroll
        for (int j = 0; j < DD / 4; j++) {
            float4 a = sq4[j];
            float4 f = tp4[j];
            dot2_step(a.x, f.x, hx, lx);
            dot2_step(a.y, f.y, hy, ly);
            dot2_step(a.z, f.z, hz, lz);
            dot2_step(a.w, f.w, hw, lw);
        }
        double v = ((double)hx + lx) + ((double)hy + ly) +
                   ((double)hz + lz) + ((double)hw + lw);
        ssim[c] = v * qinv * g_inv_tok_d[(b * NN + m) * PP + p];
    }
    __syncthreads();

    for (int k = 0; k < KTOK; k++) {
        double bv = NEG_INF_D; int bi = 0;
        for (int c = t; c < KNODE * PP; c += 256) {
            double v = ssim[c];
            if (v > bv) { bv = v; bi = c; }
        }
        rvd[t] = bv; ri[t] = bi;
        __syncthreads();
        if (t < 32) {
            double v = rvd[t]; int i = ri[t];
            #pragma unroll
            for (int j = 1; j < 8; j++) {
                double v2 = rvd[t + j * 32]; int i2 = ri[t + j * 32];
                if (v2 > v || (v2 == v && i2 < i)) { v = v2; i = i2; }
            }
            #pragma unroll
            for (int o = 16; o; o >>= 1) {
                double v2 = __shfl_xor_sync(0xffffffffu, v, o);
                int    i2 = __shfl_xor_sync(0xffffffffu, i, o);
                if (v2 > v || (v2 == v && i2 < i)) { v = v2; i = i2; }
            }
            if (t == 0) {
                int c = i; int kn = c / PP, p = c - kn * PP;
                cm[k] = snode[kn]; cp[k] = p;
                ssim[c] = NEG_INF_D;
            }
        }
        __syncthreads();
    }

    if (t < KTOK * DD / 4) {
        int k = t / (DD / 4), j = t - k * (DD / 4);
        ((float4*)stok)[t] =
            ((const float4*)(h + (((size_t)(b * NN + cm[k])) * PP + cp[k]) * DD))[j];
    }
    __syncthreads();

    float nt = ntok[0];
    for (int o = t; o < KTOK * DD; o += 256) {
        int k = o / DD, e = o - k * DD;
        float acc = bias[e] + nt;
        #pragma unroll 8
        for (int d = 0; d < DD; d++) acc += stok[k * DD + d] * sW[e * 97 + d];
        out[(((size_t)bn) * POUT + PP + k) * (size_t)DD + e] = acc;
    }
}

// =========================================================================
// K5: hf = h @ W^T + b -> out[:, :, 0:42, :].
// =========================================================================
__global__ __launch_bounds__(256) void k_hf(const float* __restrict__ h,
                                            const float* __restrict__ W,
                                            const float* __restrict__ bias,
                                            float* __restrict__ out) {
    extern __shared__ __align__(16) float dyn[];
    float* sXT = dyn;                 // [DD][68]
    float* sWT = dyn + DD * 68;       // [DD][98]

    int r0 = blockIdx.x * 64;
    int t = threadIdx.x;

    const float* Xbase = h + (size_t)r0 * DD;
    for (int i = t; i < 64 * DD; i += 256) {
        int r = i / DD, d = i - r * DD;
        sXT[d * 68 + r] = Xbase[i];
    }
    for (int i = t; i < DD * DD; i += 256) {
        int e = i / DD, d = i - e * DD;
        sWT[d * 98 + e] = W[i];
    }
    __syncthreads();

    int tx = t & 15, ty = t >> 4;
    float acc[4][6];
    #pragma unroll
    for (int i = 0; i < 4; i++)
        #pragma unroll
        for (int j = 0; j < 6; j++) acc[i][j] = bias[tx * 6 + j];

    #pragma unroll 4
    for (int d = 0; d < DD; d++) {
        float4 xv = *(const float4*)(sXT + d * 68 + ty * 4);
        float2 w0 = *(const float2*)(sWT + d * 98 + tx * 6);
        float2 w1 = *(const float2*)(sWT + d * 98 + tx * 6 + 2);
        float2 w2 = *(const float2*)(sWT + d * 98 + tx * 6 + 4);
        float x[4] = {xv.x, xv.y, xv.z, xv.w};
        float w[6] = {w0.x, w0.y, w1.x, w1.y, w2.x, w2.y};
        #pragma unroll
        for (int i = 0; i < 4; i++)
            #pragma unroll
            for (int j = 0; j < 6; j++) acc[i][j] += x[i] * w[j];
    }

    #pragma unroll
    for (int i = 0; i < 4; i++) {
        int r = r0 + ty * 4 + i;
        int bn = r / PP, p = r - bn * PP;
        float* orow = out + (((size_t)bn) * POUT + p) * (size_t)DD + tx * 6;
        #pragma unroll
        for (int j = 0; j < 6; j++) orow[j] = acc[i][j];
    }
}

// =========================================================================
extern "C" void kernel_launch(void* const* d_in, const int* in_sizes, int n_in,
                              void* d_out, int out_size) {
    const float* h    = (const float*)d_in[0];
    const float* W    = (const float*)d_in[1];
    const float* bias = (const float*)d_in[2];
    const float* ntok = (const float*)d_in[3];
    float* out = (float*)d_out;

    // Launch order puts k_sim_mma 4th so ncu (which captures launch #4)
    // profiles the dominant kernel.  Dependencies preserved.
    k_norms<<<BB * NN, 128>>>(h);                                    // 1
    k_conv<<<(BB * NN * PD) / (256 * 4), 256>>>(h);                  // 2

    size_t hf_smem = (size_t)(DD * 68 + DD * 98) * sizeof(float);
    cudaFuncSetAttribute(k_hf, cudaFuncAttributeMaxDynamicSharedMemorySize, (int)hf_smem);
    k_hf<<<(BB * NN * PP) / 64, 256, hf_smem>>>(h, W, bias, out);    // 3

    cudaFuncSetAttribute(k_sim_mma, cudaFuncAttributeMaxDynamicSharedMemorySize, 65536);
    dim3 g2(NN / 128, NN / 128, BB);
    k_sim_mma<<<g2, 256, 65536>>>();                                 // 4  <- profiled

    k_topk_node<<<BB * NN, 256>>>();                                 // 5

    k_rerank<<<BB * NN, 384>>>(h);                                   // 6

    size_t tok_smem = (336 + 256) * sizeof(double) +
                      (DD + KTOK * DD + DD * 97) * sizeof(float) +
                      (256 + KNODE + KTOK + KTOK) * sizeof(int);
    cudaFuncSetAttribute(k_tok, cudaFuncAttributeMaxDynamicSharedMemorySize, (int)tok_smem);
    k_tok<<<BB * NN, 256, tok_smem>>>(h, W, bias, ntok, out);        // 7
}